// round 15
// baseline (speedup 1.0000x reference)
#include <cuda_runtime.h>

// net_LSTM_21534966022336: T=4096, B=8192, I=H=1 -> 8192 independent scalar
// LSTM chains. Single-chain optimum (R8): 101 cyc/step = 2x16 (MUFU lat)
// + ~25 issue offsets + ~45 SB-wakeup over ~4 wait points. This round:
// TWO chains per thread, manually ABAB-interleaved, with SLIM x-rings
// (16/chain, 2 phases) so ptxas keeps scheduling freedom (R9 died at 254
// regs). Chain B's instructions fill chain A's MUFU waits -> waits
// pre-drained, pair-period -> max(MUFU port 64, deps ~85) < 2x101.

#ifndef LSTM_T
#define LSTM_T 4096
#endif
#ifndef LSTM_B
#define LSTM_B 8192
#endif

__device__ __forceinline__ float tanh_approx(float v) {
    float y;
    asm("tanh.approx.f32 %0, %1;" : "=f"(y) : "f"(v));
    return y;
}

__global__ void __launch_bounds__(128, 1)
lstm_scalar_chain_kernel(const float* __restrict__ x,
                         const float* __restrict__ h0,
                         const float* __restrict__ c0,
                         const float* __restrict__ w_ih,
                         const float* __restrict__ w_hh,
                         float* __restrict__ out,
                         int out_size) {
    const int b = blockIdx.x * blockDim.x + threadIdx.x;
    constexpr int HB = LSTM_B / 2;
    if (b >= HB) return;

    // Pre-scaled shared scalar weights (gate order i, f, g, o).
    const float wi_i = 0.50f * w_ih[0];
    const float wi_f = 0.50f * w_ih[1];
    const float wi_g =         w_ih[2];
    const float wi_o = 0.50f * w_ih[3];
    const float wh_i = 0.25f * w_hh[0];
    const float wh_f = 0.25f * w_hh[1];
    const float wh_g = 0.50f * w_hh[2];
    const float wh_o = 0.25f * w_hh[3];

    // Two independent chains per thread: A = b, B = b + HB.
    // Seed: tc*(1+to) = 2*h0 -> tc = 2*h0, to = 0 (exact).
    float tcA = 2.0f * h0[b],      toA = 0.0f, cA = c0[b],      hpA = 0.0f;
    float tcB = 2.0f * h0[b + HB], toB = 0.0f, cB = c0[b + HB], hpB = 0.0f;

    const float* xpA = x + b;
    float*       opA = out + b;

    // Slim 2-phase rings: 8 steps per phase per chain (16 regs/chain).
    float xrA[16], xrB[16];
#pragma unroll
    for (int u = 0; u < 16; ++u) xrA[u] = xpA[u * LSTM_B];
#pragma unroll
    for (int u = 0; u < 16; ++u) xrB[u] = xpA[u * LSTM_B + HB];

    // One fused pair-step, ABAB interleaved so MUFU port slots alternate
    // chains and both terminal deps stay symmetric.
#define LSTM_STEP_PAIR(xvA, xvB, t_store)                                  \
    {                                                                      \
        const float xfA = (xvA) * wi_f;  const float xfB = (xvB) * wi_f;   \
        const float xgA = (xvA) * wi_g;  const float xgB = (xvB) * wi_g;   \
        const float xiA = (xvA) * wi_i;  const float xiB = (xvB) * wi_i;   \
        const float xoA = (xvA) * wi_o;  const float xoB = (xvB) * wi_o;   \
        const float sfA = fmaf(toA, wh_f, wh_f);                           \
        const float sfB = fmaf(toB, wh_f, wh_f);                           \
        const float sgA = fmaf(toA, wh_g, wh_g);                           \
        const float sgB = fmaf(toB, wh_g, wh_g);                           \
        const float siA = fmaf(toA, wh_i, wh_i);                           \
        const float siB = fmaf(toB, wh_i, wh_i);                           \
        const float soA = fmaf(toA, wh_o, wh_o);                           \
        const float soB = fmaf(toB, wh_o, wh_o);                           \
        const float hcA = 0.5f * cA;     const float hcB = 0.5f * cB;      \
        const float afA = fmaf(tcA, sfA, xfA);                             \
        const float afB = fmaf(tcB, sfB, xfB);                             \
        const float agA = fmaf(tcA, sgA, xgA);                             \
        const float agB = fmaf(tcB, sgB, xgB);                             \
        const float aiA = fmaf(tcA, siA, xiA);                             \
        const float aiB = fmaf(tcB, siB, xiB);                             \
        const float aoA = fmaf(tcA, soA, xoA);                             \
        const float aoB = fmaf(tcB, soB, xoB);                             \
        const float tfA = tanh_approx(afA);                                \
        const float tfB = tanh_approx(afB);                                \
        const float tgA = tanh_approx(agA);                                \
        const float tgB = tanh_approx(agB);                                \
        const float tiA = tanh_approx(aiA);                                \
        const float tiB = tanh_approx(aiB);                                \
        const float toA2 = tanh_approx(aoA);                               \
        const float toB2 = tanh_approx(aoB);                               \
        opA[(t_store) * LSTM_B]      = hpA;                                \
        opA[(t_store) * LSTM_B + HB] = hpB;                                \
        const float vA   = fmaf(tfA, hcA, hcA);                            \
        const float vB   = fmaf(tfB, hcB, hcB);                            \
        const float htgA = 0.5f * tgA;   const float htgB = 0.5f * tgB;    \
        const float sA   = vA + htgA;    const float sB   = vB + htgB;     \
        cA = fmaf(tiA, htgA, sA);        cB = fmaf(tiB, htgB, sB);         \
        const float tcA2 = tanh_approx(cA);                                \
        const float tcB2 = tanh_approx(cB);                                \
        const float shoA = fmaf(toA2, 0.5f, 0.5f);                         \
        const float shoB = fmaf(toB2, 0.5f, 0.5f);                         \
        hpA = tcA2 * shoA;               hpB = tcB2 * shoB;                \
        tcA = tcA2;  toA = toA2;         tcB = tcB2;  toB = toB2;          \
    }

    for (int t0 = 0; t0 < LSTM_T; t0 += 16) {
#pragma unroll
        for (int ph = 0; ph < 2; ++ph) {
#pragma unroll
            for (int u = 0; u < 8; ++u) {
                const int t  = t0 + ph * 8 + u;
                const int ts = (t > 0) ? (t - 1) : 0;  // pipelined store idx
                LSTM_STEP_PAIR(xrA[ph * 8 + u], xrB[ph * 8 + u], ts)
            }
            // Reload this phase's buffers for t0+16 (clamped base at tail).
            {
                int tb = t0 + 16 + ph * 8;
                tb = (tb <= LSTM_T - 8) ? tb : (LSTM_T - 8);
                const float* q = xpA + tb * LSTM_B;
#pragma unroll
                for (int u = 0; u < 8; ++u) {
                    xrA[ph * 8 + u] = q[u * LSTM_B];
                    xrB[ph * 8 + u] = q[u * LSTM_B + HB];
                }
            }
        }
    }
#undef LSTM_STEP_PAIR

    // Final pending outputs (t = T-1), then h_n, c_n (tuple flattening order).
    opA[(LSTM_T - 1) * LSTM_B]      = hpA;
    opA[(LSTM_T - 1) * LSTM_B + HB] = hpB;
    if (out_size >= LSTM_T * LSTM_B + 2 * LSTM_B) {
        out[LSTM_T * LSTM_B + b]               = hpA;
        out[LSTM_T * LSTM_B + b + HB]          = hpB;
        out[LSTM_T * LSTM_B + LSTM_B + b]      = cA;
        out[LSTM_T * LSTM_B + LSTM_B + b + HB] = cB;
    }
}

extern "C" void kernel_launch(void* const* d_in, const int* in_sizes, int n_in,
                              void* d_out, int out_size) {
    const float* x    = (const float*)d_in[0];
    const float* h0   = (const float*)d_in[1];
    const float* c0   = (const float*)d_in[2];
    const float* w_ih = (const float*)d_in[3];
    const float* w_hh = (const float*)d_in[4];
    float* out = (float*)d_out;

    // 4096 threads, two chains each: 32 blocks x 128.
    const int threads = 128;
    const int blocks  = (LSTM_B / 2 + threads - 1) / threads;
    lstm_scalar_chain_kernel<<<blocks, threads>>>(x, h0, c0, w_ih, w_hh, out, out_size);
}

// round 16
// speedup vs baseline: 1.2640x; 1.2640x over previous
#include <cuda_runtime.h>

// net_LSTM_21534966022336: T=4096, B=8192, I=H=1 -> 8192 independent scalar
// LSTM chains; latency-bound at ~101 cyc/step (architectural floor):
//   2 x (MUFU.TANH eff RAW ~39 incl SB-wakeup) + rt=8 port spread (+16)
//   + terminal FFMA + issue offsets.
// Falsified levers (kept for the record): gate-tanh polynomial (R6/R7,
// poly depth ~= L), in-thread chain interleave (R9/R15, wakeups serialize
// regardless of independent work). Champion structure = R5 dataflow +
// one-step-pipelined store (R8). This round: store issued at the top of
// the step (tc-wait shadow) + 16-step ring so the body fits L0 I$.

#ifndef LSTM_T
#define LSTM_T 4096
#endif
#ifndef LSTM_B
#define LSTM_B 8192
#endif

__device__ __forceinline__ float tanh_approx(float v) {
    float y;
    asm("tanh.approx.f32 %0, %1;" : "=f"(y) : "f"(v));
    return y;
}

__global__ void __launch_bounds__(128, 1)
lstm_scalar_chain_kernel(const float* __restrict__ x,
                         const float* __restrict__ h0,
                         const float* __restrict__ c0,
                         const float* __restrict__ w_ih,
                         const float* __restrict__ w_hh,
                         float* __restrict__ out,
                         int out_size) {
    const int b = blockIdx.x * blockDim.x + threadIdx.x;
    if (b >= LSTM_B) return;

    // Pre-scaled shared scalar weights (gate order i, f, g, o).
    const float wi_i = 0.50f * w_ih[0];
    const float wi_f = 0.50f * w_ih[1];
    const float wi_g =         w_ih[2];
    const float wi_o = 0.50f * w_ih[3];
    const float wh_i = 0.25f * w_hh[0];
    const float wh_f = 0.25f * w_hh[1];
    const float wh_g = 0.50f * w_hh[2];
    const float wh_o = 0.25f * w_hh[3];

    // Seed: tc*(1+to) = 2*h0 -> tc = 2*h0, to = 0 (exact).
    float tc = 2.0f * h0[b];
    float to = 0.0f;
    float c  = c0[b];

    // Pending output store (h of previous step), pipelined by one step.
    // Deterministic dummy for the first store (overwritten at t==1).
    float h_pend = 0.0f;

    const float* xp = x + b;
    float*       op = out + b;

    // 2-phase ring of 8-wide x buffers (16 steps resident), reloaded in
    // place after consumption; prefetch distance 8-16 steps (~1000+ cyc at
    // 101 cyc/step) comfortably covers DRAM latency.
    float xr[16];
#pragma unroll
    for (int u = 0; u < 16; ++u) xr[u] = xp[u * LSTM_B];

    for (int t0 = 0; t0 < LSTM_T; t0 += 16) {
#pragma unroll
        for (int ph = 0; ph < 2; ++ph) {
#pragma unroll
            for (int u = 0; u < 8; ++u) {
                const int t = t0 + ph * 8 + u;
                const float xv = xr[ph * 8 + u];

                // Pipelined store first: operand ready ~1 period ago, so it
                // issues inside the tc-wait shadow, never ahead of critical
                // FFMAs. (t==0 instance is compile-time resolved: ph==0,u==0
                // only clamps in the first outer iteration via ts.)
                const int ts = (t > 0) ? (t - 1) : 0;
                op[ts * LSTM_B] = h_pend;

                // Off-path operands, ready before tc lands:
                const float xf = xv * wi_f;
                const float xg = xv * wi_g;
                const float xi = xv * wi_i;
                const float xo = xv * wi_o;
                const float sf = fmaf(to, wh_f, wh_f);
                const float sg = fmaf(to, wh_g, wh_g);
                const float si = fmaf(to, wh_i, wh_i);
                const float so = fmaf(to, wh_o, wh_o);
                const float hc = 0.5f * c;

                // Critical: one FFMA after tc, straight into MUFU (f,g,i).
                const float af = fmaf(tc, sf, xf);
                const float ag = fmaf(tc, sg, xg);
                const float ai = fmaf(tc, si, xi);
                const float tf = tanh_approx(af);   // port +5
                const float tg = tanh_approx(ag);   // port +13
                const float ti = tanh_approx(ai);   // port +21 (terminal)

                // o-gate MUFU: off-path (consumed next step).
                const float ao  = fmaf(tc, so, xo);
                const float to2 = tanh_approx(ao);

                // c' = sigmoid(f)*c + sigmoid(i)*tanh(g); exactly one FFMA
                // after the 3rd MUFU (ti) -- optimal binding.
                const float v   = fmaf(tf, hc, hc);
                const float htg = 0.5f * tg;
                const float s   = v + htg;
                c = fmaf(ti, htg, s);

                const float tc2 = tanh_approx(c);

                // h = sigmoid(o)*tanh(c); computed now, stored next step.
                const float sho = fmaf(to2, 0.5f, 0.5f);
                h_pend = tc2 * sho;

                tc = tc2;
                to = to2;
            }
            // Reload this phase's buffer for t0+16; single clamped base per
            // phase (tail loads valid-but-unused).
            {
                int tb = t0 + 16 + ph * 8;
                tb = (tb <= LSTM_T - 8) ? tb : (LSTM_T - 8);
                const float* xq = xp + tb * LSTM_B;
#pragma unroll
                for (int u = 0; u < 8; ++u)
                    xr[ph * 8 + u] = xq[u * LSTM_B];
            }
        }
    }

    // Final pending output (t = T-1), then h_n, c_n (tuple flattening order).
    op[(LSTM_T - 1) * LSTM_B] = h_pend;
    if (out_size >= LSTM_T * LSTM_B + 2 * LSTM_B) {
        out[LSTM_T * LSTM_B + b]          = h_pend;   // h_n = last h
        out[LSTM_T * LSTM_B + LSTM_B + b] = c;        // c_n
    }
}

extern "C" void kernel_launch(void* const* d_in, const int* in_sizes, int n_in,
                              void* d_out, int out_size) {
    const float* x    = (const float*)d_in[0];
    const float* h0   = (const float*)d_in[1];
    const float* c0   = (const float*)d_in[2];
    const float* w_ih = (const float*)d_in[3];
    const float* w_hh = (const float*)d_in[4];
    float* out = (float*)d_out;

    // 8192 chains: 64 blocks x 128 threads -> exactly one warp per SMSP on
    // 64 SMs (private MUFU port per chain-warp).
    const int threads = 128;
    const int blocks  = (LSTM_B + threads - 1) / threads;
    lstm_scalar_chain_kernel<<<blocks, threads>>>(x, h0, c0, w_ih, w_hh, out, out_size);
}

// round 17
// speedup vs baseline: 1.5689x; 1.2413x over previous
#include <cuda_runtime.h>

// net_LSTM_21534966022336: T=4096, B=8192, I=H=1 -> 8192 independent scalar
// LSTM chains; latency-bound: wall = 4096 * period, period ~101 cyc =
// 2 x (MUFU.TANH eff RAW ~39 incl SB-wakeup) + rt=8 port spread + terminal
// FFMA + issue offsets. CHAMPION (R8, 211.0 us) — exact revert.
//
// Experiment record:
//  - R5 dataflow: gate MUFUs f,g,i then off-path o; terminal fma binds the
//    3rd MUFU with exactly one FFMA. Optimal binding.
//  - R8: store pipelined by one step, placed AFTER the MUFU issues (in the
//    wait shadow). WIN.
//  - Falsified: poly-gate tanh (R6/R7: poly depth ~= L, and its issue slots
//    slip the critical MUFUs); in-thread dual-chain interleave (R9 @254regs,
//    R15 @168regs: wakeups serialize regardless of independent work);
//    store-at-top + 16-ring (R16: address/STG issue ahead of critical ops +
//    lost cross-step pipelining, 101 -> 127 cyc).

#ifndef LSTM_T
#define LSTM_T 4096
#endif
#ifndef LSTM_B
#define LSTM_B 8192
#endif

__device__ __forceinline__ float tanh_approx(float v) {
    float y;
    asm("tanh.approx.f32 %0, %1;" : "=f"(y) : "f"(v));
    return y;
}

__global__ void __launch_bounds__(128, 1)
lstm_scalar_chain_kernel(const float* __restrict__ x,
                         const float* __restrict__ h0,
                         const float* __restrict__ c0,
                         const float* __restrict__ w_ih,
                         const float* __restrict__ w_hh,
                         float* __restrict__ out,
                         int out_size) {
    const int b = blockIdx.x * blockDim.x + threadIdx.x;
    if (b >= LSTM_B) return;

    // Pre-scaled shared scalar weights (gate order i, f, g, o).
    const float wi_i = 0.50f * w_ih[0];
    const float wi_f = 0.50f * w_ih[1];
    const float wi_g =         w_ih[2];
    const float wi_o = 0.50f * w_ih[3];
    const float wh_i = 0.25f * w_hh[0];
    const float wh_f = 0.25f * w_hh[1];
    const float wh_g = 0.50f * w_hh[2];
    const float wh_o = 0.25f * w_hh[3];

    // Seed: tc*(1+to) = 2*h0 -> tc = 2*h0, to = 0 (exact).
    float tc = 2.0f * h0[b];
    float to = 0.0f;
    float c  = c0[b];

    // Pending output store (h of the previous step), pipelined by one step.
    // Deterministic dummy for the very first store (overwritten by real h0).
    float h_pend = 0.0f;

    const float* xp = x + b;
    float*       op = out + b;

    // 4-phase ring of 8-wide x buffers: 32 steps resident, reloaded in place
    // right after consumption (prefetch distance = 24 steps, no rotation).
    float xr[32];
#pragma unroll
    for (int u = 0; u < 32; ++u) xr[u] = xp[u * LSTM_B];

    for (int t0 = 0; t0 < LSTM_T; t0 += 32) {
#pragma unroll
        for (int ph = 0; ph < 4; ++ph) {
#pragma unroll
            for (int u = 0; u < 8; ++u) {
                const float xv = xr[ph * 8 + u];

                // Off-path operands, ready before tc lands:
                const float xf = xv * wi_f;
                const float xg = xv * wi_g;
                const float xi = xv * wi_i;
                const float xo = xv * wi_o;
                const float sf = fmaf(to, wh_f, wh_f);
                const float sg = fmaf(to, wh_g, wh_g);
                const float si = fmaf(to, wh_i, wh_i);
                const float so = fmaf(to, wh_o, wh_o);
                const float hc = 0.5f * c;

                // Critical: one FFMA after tc, straight into MUFU (f,g,i).
                const float af = fmaf(tc, sf, xf);
                const float ag = fmaf(tc, sg, xg);
                const float ai = fmaf(tc, si, xi);
                const float tf = tanh_approx(af);   // +5
                const float tg = tanh_approx(ag);   // +13
                const float ti = tanh_approx(ai);   // +21 (terminal)

                // o-gate MUFU: off-path (consumed next step).
                const float ao  = fmaf(tc, so, xo);
                const float to2 = tanh_approx(ao);

                // Previous step's output store: data long ready, issued in
                // the gate-MUFU wait shadow. (ph==0,u==0) clamps for t0==0.
                if (ph == 0 && u == 0) {
                    int tp = t0 - 1;
                    tp = (tp > 0) ? tp : 0;
                    op[tp * LSTM_B] = h_pend;
                } else {
                    op[(t0 + ph * 8 + u - 1) * LSTM_B] = h_pend;
                }

                // c' = sigmoid(f)*c + sigmoid(i)*tanh(g); terminal fma on ti.
                const float v   = fmaf(tf, hc, hc);
                const float htg = 0.5f * tg;
                const float s   = v + htg;
                c = fmaf(ti, htg, s);

                const float tc2 = tanh_approx(c);

                // h = sigmoid(o)*tanh(c); computed now, stored next step.
                const float sho = fmaf(to2, 0.5f, 0.5f);
                h_pend = tc2 * sho;

                tc = tc2;
                to = to2;
            }
            // Reload this phase's buffer for t0+32; single clamped base
            // index per phase (tail loads valid-but-unused).
            {
                int tb = t0 + 32 + ph * 8;
                tb = (tb <= LSTM_T - 8) ? tb : (LSTM_T - 8);
                const float* xq = xp + tb * LSTM_B;
#pragma unroll
                for (int u = 0; u < 8; ++u)
                    xr[ph * 8 + u] = xq[u * LSTM_B];
            }
        }
    }

    // Final pending output (t = T-1), then h_n, c_n (tuple flattening order).
    op[(LSTM_T - 1) * LSTM_B] = h_pend;
    if (out_size >= LSTM_T * LSTM_B + 2 * LSTM_B) {
        out[LSTM_T * LSTM_B + b]          = h_pend;   // h_n = last h
        out[LSTM_T * LSTM_B + LSTM_B + b] = c;        // c_n
    }
}

extern "C" void kernel_launch(void* const* d_in, const int* in_sizes, int n_in,
                              void* d_out, int out_size) {
    const float* x    = (const float*)d_in[0];
    const float* h0   = (const float*)d_in[1];
    const float* c0   = (const float*)d_in[2];
    const float* w_ih = (const float*)d_in[3];
    const float* w_hh = (const float*)d_in[4];
    float* out = (float*)d_out;

    const int threads = 128;
    const int blocks  = (LSTM_B + threads - 1) / threads;
    lstm_scalar_chain_kernel<<<blocks, threads>>>(x, h0, c0, w_ih, w_hh, out, out_size);
}